// round 11
// baseline (speedup 1.0000x reference)
#include <cuda_runtime.h>
#include <cuda_fp16.h>

// Problem constants (fixed by the dataset shapes)
#define HWC   65536      // 256*256
#define BATCH 64
#define NATT  4096
#define MREP  2048
#define NPIX  (BATCH * HWC)          // 4,194,304

// Fused producer/consumer grid.
// blocks [0, PACKB): pack producers (dispatched FIRST -> deadlock-free)
// blocks [PACKB, PACKB+GATB): gather consumers, 16 per batch (8 repel + 8 attract)
#define PACKB 128
#define GATB  1024
#define TOTB  (PACKB + GATB)
#define CHUNKS_PER_BATCH 128         // 512-px chunks; flag target

// 32 MiB packed maps: per pixel {h, off_y, off_x, 0} as 4 x fp16 (8 bytes).
__device__ __align__(16) uint2 g_pack[NPIX];

// Per-batch readiness flags (count of completed 512-px chunks).
__device__ unsigned int g_batch_done[BATCH];

// Accumulators: [0]=S_attract, [1]=N_attract, [2]=S_repel, [3]=N_repel.
// Zero-initialized at load; finalizing block re-zeros everything for replay determinism.
__device__ double g_acc[4];
__device__ unsigned int g_done;

__device__ __forceinline__ unsigned int ld_acquire(const unsigned int* p) {
    unsigned int v;
    asm volatile("ld.acquire.gpu.u32 %0, [%1];" : "=r"(v) : "l"(p));
    return v;
}

__device__ __forceinline__ unsigned int pack2h(float a, float b) {
    __half2 h = __floats2half2_rn(a, b);
    return *reinterpret_cast<unsigned int*>(&h);
}

__device__ __forceinline__ float3 fetch_corner(const uint2* __restrict__ pk, int idx) {
    uint2 v = __ldg(pk + idx);
    __half2 ab = *reinterpret_cast<__half2*>(&v.x);
    __half2 cd = *reinterpret_cast<__half2*>(&v.y);
    float2 f0 = __half22float2(ab);
    float2 f1 = __half22float2(cd);
    return make_float3(f0.x, f0.y, f1.x);   // h, oy, ox
}

__device__ __forceinline__ float iou_f(float hA, float yA, float xA,
                                       float hB, float yB, float xB) {
    float areaA = hA * hA * 0.41f;
    float areaB = hB * hB * 0.41f;
    float y_min_max = fmaxf(yA - hA * 0.5f,         yB - hB * 0.5f);
    float x_min_max = fmaxf(xA - 0.41f * hA * 0.5f, xB - 0.41f * hB * 0.5f);
    float y_max_min = fminf(yA + hA * 0.5f,         yB + hB * 0.5f);
    float x_max_min = fminf(xA + 0.41f * hA * 0.5f, xB + 0.41f * hB * 0.5f);
    float I = fmaxf(y_max_min - y_min_max, 0.0f) * fmaxf(x_max_min - x_min_max, 0.0f);
    float U = areaA + areaB - I;
    return I / (U + 1e-6f);
}

// Block-wide reduction of (v0, v1) -> 2 double atomics. blockDim.x == 256.
__device__ __forceinline__ void block_reduce2(float v0, float v1,
                                              double* acc0, double* acc1) {
    #pragma unroll
    for (int o = 16; o > 0; o >>= 1) {
        v0 += __shfl_down_sync(0xFFFFFFFFu, v0, o);
        v1 += __shfl_down_sync(0xFFFFFFFFu, v1, o);
    }
    __shared__ float s0[8], s1[8];
    int lane = threadIdx.x & 31;
    int warp = threadIdx.x >> 5;
    if (lane == 0) { s0[warp] = v0; s1[warp] = v1; }
    __syncthreads();
    if (warp == 0) {
        v0 = (lane < 8) ? s0[lane] : 0.0f;
        v1 = (lane < 8) ? s1[lane] : 0.0f;
        #pragma unroll
        for (int o = 4; o > 0; o >>= 1) {
            v0 += __shfl_down_sync(0x000000FFu, v0, o);
            v1 += __shfl_down_sync(0x000000FFu, v1, o);
        }
        if (lane == 0) {
            atomicAdd(acc0, (double)v0);
            atomicAdd(acc1, (double)v1);
        }
    }
}

// One attract item: 4 packed gathers + per-corner IoU against the mean box.
__device__ __forceinline__ void attract_item(const uint2* __restrict__ pk,
                                             const int4 idx4, unsigned int m4,
                                             float& lsum, float& cnt) {
    int ind[4] = {idx4.x, idx4.y, idx4.z, idx4.w};
    float3 c[4];
    #pragma unroll
    for (int k = 0; k < 4; k++) c[k] = fetch_corner(pk, ind[k]);

    // OFFSETS = [[0,0],[1,0],[0,1],[1,1]] added to (oy, ox)
    const float kx[4] = {0.f, 1.f, 0.f, 1.f};
    const float ky[4] = {0.f, 0.f, 1.f, 1.f};

    float hm = 0.f, oym = 0.f, oxm = 0.f;
    float cy[4], cx[4];
    #pragma unroll
    for (int k = 0; k < 4; k++) {
        cy[k] = c[k].y + kx[k];
        cx[k] = c[k].z + ky[k];
        hm  += c[k].x;
        oym += cy[k];
        oxm += cx[k];
    }
    hm *= 0.25f; oym *= 0.25f; oxm *= 0.25f;
    float hB = __expf(hm);

    #pragma unroll
    for (int k = 0; k < 4; k++) {
        if ((m4 >> (8 * k)) & 0xFFu) {
            lsum += 1.0f - iou_f(__expf(c[k].x), cy[k], cx[k], hB, oym, oxm);
            cnt  += 1.0f;
        }
    }
}

__global__ __launch_bounds__(256)
void fused_pack_gather_kernel(const float* __restrict__ oh,
                              const float* __restrict__ ooff,
                              const float* __restrict__ pre_off,
                              const int*   __restrict__ attract,
                              const int*   __restrict__ repel,
                              const unsigned char* __restrict__ mask_att,
                              const unsigned char* __restrict__ mask_rep,
                              float* __restrict__ out) {
    int tid = threadIdx.x;

    if (blockIdx.x < PACKB) {
        // ================= PACK producer =================
        // Block t writes chunk (t + 128*k) for k = 0..63 -> exactly one 512-px
        // chunk per batch, batches swept IN ORDER. Software-pipelined prefetch.
        int t = blockIdx.x;

        float2 h2, y2, x2;
        {   // load chunk for k=0
            int p = t * 512 + tid * 2;
            const float* base = ooff;            // batch 0
            h2 = __ldg(reinterpret_cast<const float2*>(oh + p));
            y2 = __ldg(reinterpret_cast<const float2*>(base + (p & (HWC - 1))));
            x2 = __ldg(reinterpret_cast<const float2*>(base + HWC + (p & (HWC - 1))));
        }
        #pragma unroll 1
        for (int k = 0; k < BATCH; k++) {
            float2 nh, ny, nx;
            if (k + 1 < BATCH) {   // prefetch next chunk (batch k+1)
                int pn = (t + 128 * (k + 1)) * 512 + tid * 2;
                int in = pn & (HWC - 1);
                const float* base = ooff + ((size_t)(k + 1) << 17);
                nh = __ldg(reinterpret_cast<const float2*>(oh + pn));
                ny = __ldg(reinterpret_cast<const float2*>(base + in));
                nx = __ldg(reinterpret_cast<const float2*>(base + HWC + in));
            }
            // store current chunk (batch k)
            int p = (t + 128 * k) * 512 + tid * 2;
            uint4 o;
            o.x = pack2h(h2.x, y2.x);
            o.y = pack2h(x2.x, 0.0f);
            o.z = pack2h(h2.y, y2.y);
            o.w = pack2h(x2.y, 0.0f);
            *reinterpret_cast<uint4*>(&g_pack[p]) = o;

            __threadfence();
            __syncthreads();
            if (tid == 0) atomicAdd(&g_batch_done[k], 1u);

            h2 = nh; y2 = ny; x2 = nx;
        }
        return;
    }

    // ================= GATHER consumer =================
    int gb  = blockIdx.x - PACKB;   // [0, 1024)
    int b   = gb >> 4;              // batch
    int sub = gb & 15;              // 0..7 repel, 8..15 attract

    // Wait until batch b is fully packed.
    if (tid == 0) {
        while (ld_acquire(&g_batch_done[b]) < CHUNKS_PER_BATCH) __nanosleep(64);
    }
    __syncthreads();

    const uint2* pk = g_pack + ((size_t)b << 16);

    if (sub < 8) {
        // ---- repel: one thread per (b, m), 8 packed gathers ----
        int gid = b * MREP + sub * 256 + tid;

        const int4* rp = reinterpret_cast<const int4*>(repel) + (size_t)gid * 2;
        int4 i0 = __ldg(rp);
        int4 i1 = __ldg(rp + 1);
        int ind[8] = {i0.x, i0.y, i0.z, i0.w, i1.x, i1.y, i1.z, i1.w};

        float3 c[8];
        #pragma unroll
        for (int k = 0; k < 8; k++) c[k] = fetch_corner(pk, ind[k]);

        float hmean[2], y[2], x[2];
        #pragma unroll
        for (int j = 0; j < 2; j++) {
            float hs = 0.f, sy = 0.f, sx = 0.f;
            #pragma unroll
            for (int k = 0; k < 4; k++) {
                hs += c[j * 4 + k].x;
                sy += c[j * 4 + k].y;
                sx += c[j * 4 + k].z;
            }
            hmean[j] = hs * 0.25f;
            // mean of (off + OFFSETS): OFFSETS contributes +0.5 per channel
            y[j] = sy * 0.25f + 0.5f;
            x[j] = sx * 0.25f + 0.5f;
        }
        float2 po = __ldg(reinterpret_cast<const float2*>(pre_off) + gid);
        y[1] += po.x;
        x[1] += po.y;

        float v = iou_f(__expf(hmean[0]), y[0], x[0],
                        __expf(hmean[1]), y[1], x[1]);

        float lsum = 0.f, cnt = 0.f;
        if (mask_rep[gid]) { lsum = v; cnt = 1.0f; }
        block_reduce2(lsum, cnt, &g_acc[2], &g_acc[3]);
    } else {
        // ---- attract: two items per thread, 2x4 packed gathers ----
        int s2   = sub - 8;
        int gid0 = b * NATT + s2 * 512 + tid * 2;
        int w    = gid0 >> 1;

        const int4* ap = reinterpret_cast<const int4*>(attract) + gid0;
        int4 idxA = __ldg(ap);
        int4 idxB = __ldg(ap + 1);
        uint2 m2 = __ldg(reinterpret_cast<const uint2*>(mask_att) + w);

        float lsum = 0.f, cnt = 0.f;
        attract_item(pk, idxA, m2.x, lsum, cnt);
        attract_item(pk, idxB, m2.y, lsum, cnt);
        block_reduce2(lsum, cnt, &g_acc[0], &g_acc[1]);
    }

    // ---------------- last-gather-block finalize + reset ----------------
    __threadfence();
    __shared__ bool s_last;
    if (tid == 0) {
        unsigned int ticket = atomicAdd(&g_done, 1u);
        s_last = (ticket == (unsigned int)(GATB - 1));
    }
    __syncthreads();
    if (s_last && tid == 0) {
        double sa = g_acc[0], na = g_acc[1];
        double sr = g_acc[2], nr = g_acc[3];
        out[0] = (float)(sa / (na + 1e-4) + sr / (nr + 1e-4));
        g_acc[0] = 0.0; g_acc[1] = 0.0; g_acc[2] = 0.0; g_acc[3] = 0.0;
        #pragma unroll 1
        for (int i = 0; i < BATCH; i++) g_batch_done[i] = 0u;
        __threadfence();
        g_done = 0u;
    }
}

extern "C" void kernel_launch(void* const* d_in, const int* in_sizes, int n_in,
                              void* d_out, int out_size) {
    const float* output_h    = (const float*)d_in[0];  // [64,1,256,256]
    const float* output_off  = (const float*)d_in[1];  // [64,2,256,256]
    // d_in[2], d_in[3]: target_h / target_off — unused by the reference
    const float* pre_off     = (const float*)d_in[4];  // [64,2048,2]
    const int*   attract     = (const int*)  d_in[5];  // [64,4096,4]
    const int*   repel       = (const int*)  d_in[6];  // [64,2048,2,4]
    const unsigned char* mask_attract = (const unsigned char*)d_in[7];  // [64,4096,4] bool
    const unsigned char* mask_repel   = (const unsigned char*)d_in[8];  // [64,2048,1] bool
    float* out = (float*)d_out;

    fused_pack_gather_kernel<<<TOTB, 256>>>(
        output_h, output_off, pre_off, attract, repel,
        mask_attract, mask_repel, out);
}

// round 12
// speedup vs baseline: 3.3519x; 3.3519x over previous
#include <cuda_runtime.h>
#include <cuda_fp16.h>

// Problem constants (fixed by the dataset shapes)
#define HWC   65536      // 256*256
#define BATCH 64
#define NATT  4096
#define MREP  2048
#define NPIX  (BATCH * HWC)                      // 4,194,304

#define PACK_BLOCKS (NPIX / (4 * 256))           // 4096 (4 pixels/thread)

// Gather grid: R10's balanced schedule, 24 corner-gathers per thread.
#define REP_BLOCKS ((BATCH * MREP) / 256)        // 512
#define ATT_BLOCKS ((BATCH * NATT) / (2 * 256))  // 512
#define TOT_BLOCKS (REP_BLOCKS + ATT_BLOCKS)     // 1024

// 32 MiB packed maps: per pixel {h, off_y, off_x, 0} as 4 x fp16 (8 bytes).
// One 8B gather = ONE L1tex wavefront per corner (vs 3 scattered 4B loads).
__device__ __align__(16) uint2 g_pack[NPIX];

// Accumulators: [0]=S_attract, [1]=N_attract, [2]=S_repel, [3]=N_repel.
// Zero-initialized at load; finalizing block re-zeros for graph-replay determinism.
__device__ double g_acc[4];
__device__ unsigned int g_done;

// ---- cache-policy helpers ----
__device__ __forceinline__ unsigned long long mk_policy_keep() {
    unsigned long long p;
    asm("createpolicy.fractional.L2::evict_last.b64 %0, 1.0;" : "=l"(p));
    return p;
}
__device__ __forceinline__ unsigned long long mk_policy_stream() {
    unsigned long long p;
    asm("createpolicy.fractional.L2::evict_first.b64 %0, 1.0;" : "=l"(p));
    return p;
}
__device__ __forceinline__ float4 ld_stream_f4(const float4* p, unsigned long long pol) {
    float4 v;
    asm volatile("ld.global.nc.L2::cache_hint.v4.f32 {%0,%1,%2,%3}, [%4], %5;"
                 : "=f"(v.x), "=f"(v.y), "=f"(v.z), "=f"(v.w) : "l"(p), "l"(pol));
    return v;
}
__device__ __forceinline__ void st_keep_u4(uint4* p, uint4 v, unsigned long long pol) {
    asm volatile("st.global.L2::cache_hint.v4.u32 [%0], {%1,%2,%3,%4}, %5;"
                 :: "l"(p), "r"(v.x), "r"(v.y), "r"(v.z), "r"(v.w), "l"(pol)
                 : "memory");
}

// ---------------------------------------------------------------------------
// Pass 1: coalesced pack, 4 pixels per thread.
// ---------------------------------------------------------------------------
__device__ __forceinline__ unsigned int pack2h(float a, float b) {
    __half2 h = __floats2half2_rn(a, b);
    return *reinterpret_cast<unsigned int*>(&h);
}

__global__ __launch_bounds__(256)
void pack_kernel(const float* __restrict__ oh, const float* __restrict__ ooff) {
    unsigned long long pol_keep   = mk_policy_keep();
    unsigned long long pol_stream = mk_policy_stream();

    int t = blockIdx.x * 256 + threadIdx.x;  // [0, NPIX/4)
    int p = t * 4;
    int b = p >> 16;
    int i = p & (HWC - 1);
    const float* base = ooff + ((size_t)b << 17);

    float4 h4 = ld_stream_f4(reinterpret_cast<const float4*>(oh + p),        pol_stream);
    float4 y4 = ld_stream_f4(reinterpret_cast<const float4*>(base + i),       pol_stream);
    float4 x4 = ld_stream_f4(reinterpret_cast<const float4*>(base + HWC + i), pol_stream);

    uint4 o0, o1;
    o0.x = pack2h(h4.x, y4.x);  o0.y = pack2h(x4.x, 0.0f);
    o0.z = pack2h(h4.y, y4.y);  o0.w = pack2h(x4.y, 0.0f);
    o1.x = pack2h(h4.z, y4.z);  o1.y = pack2h(x4.z, 0.0f);
    o1.z = pack2h(h4.w, y4.w);  o1.w = pack2h(x4.w, 0.0f);

    uint4* dst = reinterpret_cast<uint4*>(&g_pack[p]);
    st_keep_u4(dst,     o0, pol_keep);
    st_keep_u4(dst + 1, o1, pol_keep);
}

// ---------------------------------------------------------------------------
// Pass 2: gathers + IoU + reduction (R10 body, unchanged).
// ---------------------------------------------------------------------------
__device__ __forceinline__ float3 fetch_corner(const uint2* __restrict__ pk, int idx) {
    uint2 v = __ldg(pk + idx);
    __half2 ab = *reinterpret_cast<__half2*>(&v.x);
    __half2 cd = *reinterpret_cast<__half2*>(&v.y);
    float2 f0 = __half22float2(ab);
    float2 f1 = __half22float2(cd);
    return make_float3(f0.x, f0.y, f1.x);   // h, oy, ox
}

__device__ __forceinline__ float iou_f(float hA, float yA, float xA,
                                       float hB, float yB, float xB) {
    float areaA = hA * hA * 0.41f;
    float areaB = hB * hB * 0.41f;
    float y_min_max = fmaxf(yA - hA * 0.5f,         yB - hB * 0.5f);
    float x_min_max = fmaxf(xA - 0.41f * hA * 0.5f, xB - 0.41f * hB * 0.5f);
    float y_max_min = fminf(yA + hA * 0.5f,         yB + hB * 0.5f);
    float x_max_min = fminf(xA + 0.41f * hA * 0.5f, xB + 0.41f * hB * 0.5f);
    float I = fmaxf(y_max_min - y_min_max, 0.0f) * fmaxf(x_max_min - x_min_max, 0.0f);
    float U = areaA + areaB - I;
    return I / (U + 1e-6f);
}

// Block-wide reduction of (v0, v1) -> 2 double atomics. blockDim.x == 256.
__device__ __forceinline__ void block_reduce2(float v0, float v1,
                                              double* acc0, double* acc1) {
    #pragma unroll
    for (int o = 16; o > 0; o >>= 1) {
        v0 += __shfl_down_sync(0xFFFFFFFFu, v0, o);
        v1 += __shfl_down_sync(0xFFFFFFFFu, v1, o);
    }
    __shared__ float s0[8], s1[8];
    int lane = threadIdx.x & 31;
    int warp = threadIdx.x >> 5;
    if (lane == 0) { s0[warp] = v0; s1[warp] = v1; }
    __syncthreads();
    if (warp == 0) {
        v0 = (lane < 8) ? s0[lane] : 0.0f;
        v1 = (lane < 8) ? s1[lane] : 0.0f;
        #pragma unroll
        for (int o = 4; o > 0; o >>= 1) {
            v0 += __shfl_down_sync(0x000000FFu, v0, o);
            v1 += __shfl_down_sync(0x000000FFu, v1, o);
        }
        if (lane == 0) {
            atomicAdd(acc0, (double)v0);
            atomicAdd(acc1, (double)v1);
        }
    }
}

// One attract item: 4 packed gathers + per-corner IoU against the mean box.
__device__ __forceinline__ void attract_item(const uint2* __restrict__ pk,
                                             const int4 idx4, unsigned int m4,
                                             float& lsum, float& cnt) {
    int ind[4] = {idx4.x, idx4.y, idx4.z, idx4.w};
    float3 c[4];
    #pragma unroll
    for (int k = 0; k < 4; k++) c[k] = fetch_corner(pk, ind[k]);

    // OFFSETS = [[0,0],[1,0],[0,1],[1,1]] added to (oy, ox)
    const float kx[4] = {0.f, 1.f, 0.f, 1.f};
    const float ky[4] = {0.f, 0.f, 1.f, 1.f};

    float hm = 0.f, oym = 0.f, oxm = 0.f;
    float cy[4], cx[4];
    #pragma unroll
    for (int k = 0; k < 4; k++) {
        cy[k] = c[k].y + kx[k];
        cx[k] = c[k].z + ky[k];
        hm  += c[k].x;
        oym += cy[k];
        oxm += cx[k];
    }
    hm *= 0.25f; oym *= 0.25f; oxm *= 0.25f;
    float hB = __expf(hm);

    #pragma unroll
    for (int k = 0; k < 4; k++) {
        if ((m4 >> (8 * k)) & 0xFFu) {
            lsum += 1.0f - iou_f(__expf(c[k].x), cy[k], cx[k], hB, oym, oxm);
            cnt  += 1.0f;
        }
    }
}

__global__ __launch_bounds__(256, 8)
void gather_kernel(const float* __restrict__ pre_off,
                   const int*   __restrict__ attract,
                   const int*   __restrict__ repel,
                   const unsigned char* __restrict__ mask_att,
                   const unsigned char* __restrict__ mask_rep,
                   float* __restrict__ out) {
    if (blockIdx.x < REP_BLOCKS) {
        // ------------- repel: one thread per (b, m), 8 packed gathers -------------
        int gid = blockIdx.x * 256 + threadIdx.x;   // b*MREP + m
        int b   = gid >> 11;                        // / 2048
        const uint2* pk = g_pack + ((size_t)b << 16);

        const int4* rp = reinterpret_cast<const int4*>(repel) + (size_t)gid * 2;
        int4 i0 = __ldg(rp);
        int4 i1 = __ldg(rp + 1);
        int ind[8] = {i0.x, i0.y, i0.z, i0.w, i1.x, i1.y, i1.z, i1.w};

        float3 c[8];
        #pragma unroll
        for (int k = 0; k < 8; k++) c[k] = fetch_corner(pk, ind[k]);

        float hmean[2], y[2], x[2];
        #pragma unroll
        for (int j = 0; j < 2; j++) {
            float hs = 0.f, sy = 0.f, sx = 0.f;
            #pragma unroll
            for (int k = 0; k < 4; k++) {
                hs += c[j * 4 + k].x;
                sy += c[j * 4 + k].y;
                sx += c[j * 4 + k].z;
            }
            hmean[j] = hs * 0.25f;
            // mean of (off + OFFSETS): OFFSETS contributes +0.5 per channel
            y[j] = sy * 0.25f + 0.5f;
            x[j] = sx * 0.25f + 0.5f;
        }
        float2 po = __ldg(reinterpret_cast<const float2*>(pre_off) + gid);
        y[1] += po.x;
        x[1] += po.y;

        float v = iou_f(__expf(hmean[0]), y[0], x[0],
                        __expf(hmean[1]), y[1], x[1]);

        float lsum = 0.f, cnt = 0.f;
        if (mask_rep[gid]) { lsum = v; cnt = 1.0f; }
        block_reduce2(lsum, cnt, &g_acc[2], &g_acc[3]);
    } else {
        // ----------- attract: two items per thread, 2x4 packed gathers -----------
        int w = (blockIdx.x - REP_BLOCKS) * 256 + threadIdx.x;  // [0, B*NATT/2)
        int gid0 = 2 * w;
        int b = gid0 >> 12;                                     // / 4096
        const uint2* pk = g_pack + ((size_t)b << 16);

        const int4* ap = reinterpret_cast<const int4*>(attract) + gid0;
        int4 idxA = __ldg(ap);
        int4 idxB = __ldg(ap + 1);
        uint2 m2 = __ldg(reinterpret_cast<const uint2*>(mask_att) + w);

        float lsum = 0.f, cnt = 0.f;
        attract_item(pk, idxA, m2.x, lsum, cnt);
        attract_item(pk, idxB, m2.y, lsum, cnt);
        block_reduce2(lsum, cnt, &g_acc[0], &g_acc[1]);
    }

    // ---------------- last-block finalize + reset ----------------
    __threadfence();
    __shared__ bool s_last;
    if (threadIdx.x == 0) {
        unsigned int ticket = atomicAdd(&g_done, 1u);
        s_last = (ticket == (unsigned int)(TOT_BLOCKS - 1));
    }
    __syncthreads();
    if (s_last && threadIdx.x == 0) {
        double sa = g_acc[0], na = g_acc[1];
        double sr = g_acc[2], nr = g_acc[3];
        out[0] = (float)(sa / (na + 1e-4) + sr / (nr + 1e-4));
        g_acc[0] = 0.0; g_acc[1] = 0.0; g_acc[2] = 0.0; g_acc[3] = 0.0;
        __threadfence();
        g_done = 0u;
    }
}

extern "C" void kernel_launch(void* const* d_in, const int* in_sizes, int n_in,
                              void* d_out, int out_size) {
    const float* output_h    = (const float*)d_in[0];  // [64,1,256,256]
    const float* output_off  = (const float*)d_in[1];  // [64,2,256,256]
    // d_in[2], d_in[3]: target_h / target_off — unused by the reference
    const float* pre_off     = (const float*)d_in[4];  // [64,2048,2]
    const int*   attract     = (const int*)  d_in[5];  // [64,4096,4]
    const int*   repel       = (const int*)  d_in[6];  // [64,2048,2,4]
    const unsigned char* mask_attract = (const unsigned char*)d_in[7];  // [64,4096,4] bool
    const unsigned char* mask_repel   = (const unsigned char*)d_in[8];  // [64,2048,1] bool
    float* out = (float*)d_out;

    pack_kernel<<<PACK_BLOCKS, 256>>>(output_h, output_off);
    gather_kernel<<<TOT_BLOCKS, 256>>>(pre_off, attract, repel,
                                       mask_attract, mask_repel, out);
}

// round 13
// speedup vs baseline: 3.3871x; 1.0105x over previous
#include <cuda_runtime.h>
#include <cuda_fp16.h>

// Problem constants (fixed by the dataset shapes)
#define HWC   65536      // 256*256
#define BATCH 64
#define NATT  4096
#define MREP  2048
#define NPIX  (BATCH * HWC)                      // 4,194,304

#define PACK_BLOCKS (NPIX / (4 * 256))           // 4096 (4 pixels/thread)

// Gather grid: balanced schedule, 24 corner-gathers per thread.
#define REP_BLOCKS ((BATCH * MREP) / 256)        // 512
#define ATT_BLOCKS ((BATCH * NATT) / (2 * 256))  // 512
#define TOT_BLOCKS (REP_BLOCKS + ATT_BLOCKS)     // 1024

// 32 MiB packed maps: per pixel {h, off_y, off_x, 0} as 4 x fp16 (8 bytes).
// One 8B gather = ONE L1tex wavefront per corner (vs 3 scattered 4B loads).
__device__ __align__(16) uint2 g_pack[NPIX];

// Accumulators: [0]=S_attract, [1]=N_attract, [2]=S_repel, [3]=N_repel.
// Zero-initialized at load; finalizing block re-zeros for graph-replay determinism.
__device__ double g_acc[4];
__device__ unsigned int g_done;

// ---------------------------------------------------------------------------
// Pass 1: coalesced pack, 4 pixels per thread.
// ---------------------------------------------------------------------------
__device__ __forceinline__ unsigned int pack2h(float a, float b) {
    __half2 h = __floats2half2_rn(a, b);
    return *reinterpret_cast<unsigned int*>(&h);
}

__global__ __launch_bounds__(256)
void pack_kernel(const float* __restrict__ oh, const float* __restrict__ ooff) {
    int t = blockIdx.x * 256 + threadIdx.x;  // [0, NPIX/4)
    int p = t * 4;
    int b = p >> 16;
    int i = p & (HWC - 1);
    const float* base = ooff + ((size_t)b << 17);

    float4 h4 = __ldg(reinterpret_cast<const float4*>(oh + p));
    float4 y4 = __ldg(reinterpret_cast<const float4*>(base + i));
    float4 x4 = __ldg(reinterpret_cast<const float4*>(base + HWC + i));

    uint4 o0, o1;
    o0.x = pack2h(h4.x, y4.x);  o0.y = pack2h(x4.x, 0.0f);
    o0.z = pack2h(h4.y, y4.y);  o0.w = pack2h(x4.y, 0.0f);
    o1.x = pack2h(h4.z, y4.z);  o1.y = pack2h(x4.z, 0.0f);
    o1.z = pack2h(h4.w, y4.w);  o1.w = pack2h(x4.w, 0.0f);

    uint4* dst = reinterpret_cast<uint4*>(&g_pack[p]);
    dst[0] = o0;
    dst[1] = o1;

    // Release the dependent gather launch as soon as our stores are issued.
    cudaTriggerProgrammaticLaunchCompletion();
}

// ---------------------------------------------------------------------------
// Pass 2: gathers + IoU + reduction. Launched with PDL: index/mask streams
// load BEFORE the dependency fence (overlapping pack), gathers after.
// ---------------------------------------------------------------------------
__device__ __forceinline__ float3 fetch_corner(const uint2* __restrict__ pk, int idx) {
    uint2 v = __ldg(pk + idx);
    __half2 ab = *reinterpret_cast<__half2*>(&v.x);
    __half2 cd = *reinterpret_cast<__half2*>(&v.y);
    float2 f0 = __half22float2(ab);
    float2 f1 = __half22float2(cd);
    return make_float3(f0.x, f0.y, f1.x);   // h, oy, ox
}

__device__ __forceinline__ float iou_f(float hA, float yA, float xA,
                                       float hB, float yB, float xB) {
    float areaA = hA * hA * 0.41f;
    float areaB = hB * hB * 0.41f;
    float y_min_max = fmaxf(yA - hA * 0.5f,         yB - hB * 0.5f);
    float x_min_max = fmaxf(xA - 0.41f * hA * 0.5f, xB - 0.41f * hB * 0.5f);
    float y_max_min = fminf(yA + hA * 0.5f,         yB + hB * 0.5f);
    float x_max_min = fminf(xA + 0.41f * hA * 0.5f, xB + 0.41f * hB * 0.5f);
    float I = fmaxf(y_max_min - y_min_max, 0.0f) * fmaxf(x_max_min - x_min_max, 0.0f);
    float U = areaA + areaB - I;
    return I / (U + 1e-6f);
}

// Block-wide reduction of (v0, v1) -> 2 double atomics. blockDim.x == 256.
__device__ __forceinline__ void block_reduce2(float v0, float v1,
                                              double* acc0, double* acc1) {
    #pragma unroll
    for (int o = 16; o > 0; o >>= 1) {
        v0 += __shfl_down_sync(0xFFFFFFFFu, v0, o);
        v1 += __shfl_down_sync(0xFFFFFFFFu, v1, o);
    }
    __shared__ float s0[8], s1[8];
    int lane = threadIdx.x & 31;
    int warp = threadIdx.x >> 5;
    if (lane == 0) { s0[warp] = v0; s1[warp] = v1; }
    __syncthreads();
    if (warp == 0) {
        v0 = (lane < 8) ? s0[lane] : 0.0f;
        v1 = (lane < 8) ? s1[lane] : 0.0f;
        #pragma unroll
        for (int o = 4; o > 0; o >>= 1) {
            v0 += __shfl_down_sync(0x000000FFu, v0, o);
            v1 += __shfl_down_sync(0x000000FFu, v1, o);
        }
        if (lane == 0) {
            atomicAdd(acc0, (double)v0);
            atomicAdd(acc1, (double)v1);
        }
    }
}

// One attract item: 4 packed gathers + per-corner IoU against the mean box.
__device__ __forceinline__ void attract_item(const uint2* __restrict__ pk,
                                             const int4 idx4, unsigned int m4,
                                             float& lsum, float& cnt) {
    int ind[4] = {idx4.x, idx4.y, idx4.z, idx4.w};
    float3 c[4];
    #pragma unroll
    for (int k = 0; k < 4; k++) c[k] = fetch_corner(pk, ind[k]);

    // OFFSETS = [[0,0],[1,0],[0,1],[1,1]] added to (oy, ox)
    const float kx[4] = {0.f, 1.f, 0.f, 1.f};
    const float ky[4] = {0.f, 0.f, 1.f, 1.f};

    float hm = 0.f, oym = 0.f, oxm = 0.f;
    float cy[4], cx[4];
    #pragma unroll
    for (int k = 0; k < 4; k++) {
        cy[k] = c[k].y + kx[k];
        cx[k] = c[k].z + ky[k];
        hm  += c[k].x;
        oym += cy[k];
        oxm += cx[k];
    }
    hm *= 0.25f; oym *= 0.25f; oxm *= 0.25f;
    float hB = __expf(hm);

    #pragma unroll
    for (int k = 0; k < 4; k++) {
        if ((m4 >> (8 * k)) & 0xFFu) {
            lsum += 1.0f - iou_f(__expf(c[k].x), cy[k], cx[k], hB, oym, oxm);
            cnt  += 1.0f;
        }
    }
}

__global__ __launch_bounds__(256, 8)
void gather_kernel(const float* __restrict__ pre_off,
                   const int*   __restrict__ attract,
                   const int*   __restrict__ repel,
                   const unsigned char* __restrict__ mask_att,
                   const unsigned char* __restrict__ mask_rep,
                   float* __restrict__ out) {
    if (blockIdx.x < REP_BLOCKS) {
        // ------------- repel: one thread per (b, m), 8 packed gathers -------------
        int gid = blockIdx.x * 256 + threadIdx.x;   // b*MREP + m
        int b   = gid >> 11;                        // / 2048
        const uint2* pk = g_pack + ((size_t)b << 16);

        // ---- pack-independent streams first (overlap with pack via PDL) ----
        const int4* rp = reinterpret_cast<const int4*>(repel) + (size_t)gid * 2;
        int4 i0 = __ldg(rp);
        int4 i1 = __ldg(rp + 1);
        float2 po = __ldg(reinterpret_cast<const float2*>(pre_off) + gid);
        unsigned char mr = mask_rep[gid];

        // ---- wait for pack to finish before touching g_pack ----
        cudaGridDependencySynchronize();

        int ind[8] = {i0.x, i0.y, i0.z, i0.w, i1.x, i1.y, i1.z, i1.w};
        float3 c[8];
        #pragma unroll
        for (int k = 0; k < 8; k++) c[k] = fetch_corner(pk, ind[k]);

        float hmean[2], y[2], x[2];
        #pragma unroll
        for (int j = 0; j < 2; j++) {
            float hs = 0.f, sy = 0.f, sx = 0.f;
            #pragma unroll
            for (int k = 0; k < 4; k++) {
                hs += c[j * 4 + k].x;
                sy += c[j * 4 + k].y;
                sx += c[j * 4 + k].z;
            }
            hmean[j] = hs * 0.25f;
            // mean of (off + OFFSETS): OFFSETS contributes +0.5 per channel
            y[j] = sy * 0.25f + 0.5f;
            x[j] = sx * 0.25f + 0.5f;
        }
        y[1] += po.x;
        x[1] += po.y;

        float v = iou_f(__expf(hmean[0]), y[0], x[0],
                        __expf(hmean[1]), y[1], x[1]);

        float lsum = 0.f, cnt = 0.f;
        if (mr) { lsum = v; cnt = 1.0f; }
        block_reduce2(lsum, cnt, &g_acc[2], &g_acc[3]);
    } else {
        // ----------- attract: two items per thread, 2x4 packed gathers -----------
        int w = (blockIdx.x - REP_BLOCKS) * 256 + threadIdx.x;  // [0, B*NATT/2)
        int gid0 = 2 * w;
        int b = gid0 >> 12;                                     // / 4096
        const uint2* pk = g_pack + ((size_t)b << 16);

        // ---- pack-independent streams first (overlap with pack via PDL) ----
        const int4* ap = reinterpret_cast<const int4*>(attract) + gid0;
        int4 idxA = __ldg(ap);
        int4 idxB = __ldg(ap + 1);
        uint2 m2 = __ldg(reinterpret_cast<const uint2*>(mask_att) + w);

        // ---- wait for pack to finish before touching g_pack ----
        cudaGridDependencySynchronize();

        float lsum = 0.f, cnt = 0.f;
        attract_item(pk, idxA, m2.x, lsum, cnt);
        attract_item(pk, idxB, m2.y, lsum, cnt);
        block_reduce2(lsum, cnt, &g_acc[0], &g_acc[1]);
    }

    // ---------------- last-block finalize + reset ----------------
    __threadfence();
    __shared__ bool s_last;
    if (threadIdx.x == 0) {
        unsigned int ticket = atomicAdd(&g_done, 1u);
        s_last = (ticket == (unsigned int)(TOT_BLOCKS - 1));
    }
    __syncthreads();
    if (s_last && threadIdx.x == 0) {
        double sa = g_acc[0], na = g_acc[1];
        double sr = g_acc[2], nr = g_acc[3];
        out[0] = (float)(sa / (na + 1e-4) + sr / (nr + 1e-4));
        g_acc[0] = 0.0; g_acc[1] = 0.0; g_acc[2] = 0.0; g_acc[3] = 0.0;
        __threadfence();
        g_done = 0u;
    }
}

extern "C" void kernel_launch(void* const* d_in, const int* in_sizes, int n_in,
                              void* d_out, int out_size) {
    const float* output_h    = (const float*)d_in[0];  // [64,1,256,256]
    const float* output_off  = (const float*)d_in[1];  // [64,2,256,256]
    // d_in[2], d_in[3]: target_h / target_off — unused by the reference
    const float* pre_off     = (const float*)d_in[4];  // [64,2048,2]
    const int*   attract     = (const int*)  d_in[5];  // [64,4096,4]
    const int*   repel       = (const int*)  d_in[6];  // [64,2048,2,4]
    const unsigned char* mask_attract = (const unsigned char*)d_in[7];  // [64,4096,4] bool
    const unsigned char* mask_repel   = (const unsigned char*)d_in[8];  // [64,2048,1] bool
    float* out = (float*)d_out;

    // Pack launch (normal).
    pack_kernel<<<PACK_BLOCKS, 256>>>(output_h, output_off);

    // Gather launch with Programmatic Dependent Launch: blocks may start while
    // pack is still running; they prefetch index/mask streams, then block at
    // cudaGridDependencySynchronize() until pack triggers completion.
    cudaLaunchConfig_t cfg = {};
    cfg.gridDim  = dim3(TOT_BLOCKS, 1, 1);
    cfg.blockDim = dim3(256, 1, 1);
    cfg.dynamicSmemBytes = 0;
    cfg.stream = 0;  // same (capture) stream as the <<<>>> launch above
    cudaLaunchAttribute attrs[1];
    attrs[0].id = cudaLaunchAttributeProgrammaticStreamSerialization;
    attrs[0].val.programmaticStreamSerializationAllowed = 1;
    cfg.attrs = attrs;
    cfg.numAttrs = 1;
    cudaLaunchKernelEx(&cfg, gather_kernel,
                       pre_off, attract, repel, mask_attract, mask_repel, out);
}